// round 1
// baseline (speedup 1.0000x reference)
#include <cuda_runtime.h>

#define NN    64          // nodes per graph
#define HID   32
#define NE    1024        // edges per graph
#define NF    3
#define NROWS (NE + NF)   // 1027
#define T     512         // threads per block

// CSR scratch (edge list is identical for every graph)
__device__ int g_off[NN + 1];
__device__ int g_sdst[NE];
__device__ int g_seidx[NE];

// ---------------------------------------------------------------------------
// Kernel 0: deterministic stable counting-sort of the 1024-edge list by src.
// Rank = #earlier edges with same src -> fully deterministic output order.
// ---------------------------------------------------------------------------
__global__ void build_csr(const int* __restrict__ esrc,
                          const int* __restrict__ edst) {
    __shared__ int ssrc[NE];
    __shared__ int cnt[NN];
    __shared__ int offs[NN + 1];
    int t = threadIdx.x;            // blockDim = NE
    if (t < NN) cnt[t] = 0;
    __syncthreads();
    int s = esrc[t];
    ssrc[t] = s;
    atomicAdd(&cnt[s], 1);          // integer counts: order-independent
    __syncthreads();
    if (t == 0) {
        int acc = 0;
        for (int n = 0; n < NN; n++) { offs[n] = acc; acc += cnt[n]; }
        offs[NN] = acc;
    }
    __syncthreads();
    int rank = 0;
    for (int e = 0; e < t; e++) rank += (ssrc[e] == s);
    int pos = offs[s] + rank;
    g_sdst[pos]  = edst[t];
    g_seidx[pos] = t;
    if (t <= NN) g_off[t] = offs[t];
}

// ---------------------------------------------------------------------------
// Kernel 1: one block per graph. Entire graph state lives in shared memory.
// ---------------------------------------------------------------------------
// shared layout (floats):
//  W1s 320 | b1s 32 | W2s 1024 | b2s 32 | Wls 2336 | bls 32 | Wvs 32 |
//  xs 256 | p1s 2048 | p2s 2048 | Hs 2048 | hsm 2304 | g1s 2048 | g2s 2048 |
//  eas 2048 | acts 1027 | wsum 16 | (ints) offs 65 | srcs 1024 | dsts 1024 | sdst 1024
#define SMEM_WORDS (320+32+1024+32+2336+32+32+256+2048+2048+2048+2304+2048+2048+2048+1027+16 + 65+1024+1024+1024)
#define SMEM_BYTES (SMEM_WORDS * 4)

__global__ __launch_bounds__(T, 2) void critic_kernel(
    const float* __restrict__ x,         // [B*64, 4]
    const float* __restrict__ edge_attr, // [B*1024, 2]
    const float* __restrict__ action,    // [B, 1027]
    const int*   __restrict__ esrc,      // [1024]
    const int*   __restrict__ edst,      // [1024]
    const float* __restrict__ W1,        // [10,32]
    const float* __restrict__ b1,        // [32]
    const float* __restrict__ W2,        // [32,32]
    const float* __restrict__ b2,        // [32]
    const float* __restrict__ Wl,        // [73,32]
    const float* __restrict__ bl,        // [32]
    const float* __restrict__ Wv,        // [32]
    const float* __restrict__ bv,        // [1]
    float* __restrict__ out)             // [B]
{
    extern __shared__ float sm[];
    float* W1s = sm;                 // 320
    float* b1s = W1s + 320;          // 32
    float* W2s = b1s + 32;           // 1024
    float* b2s = W2s + 1024;         // 32
    float* Wls = b2s + 32;           // 2336
    float* bls = Wls + 2336;         // 32
    float* Wvs = bls + 32;           // 32
    float* xs  = Wvs + 32;           // 256
    float* p1s = xs  + 256;          // 2048
    float* p2s = p1s + 2048;         // 2048
    float* Hs  = p2s + 2048;         // 2048
    float* hsm = Hs  + 2048;         // 2304 (64 x 36)
    float* g1s = hsm + 2304;         // 2048
    float* g2s = g1s + 2048;         // 2048
    float* eas = g2s + 2048;         // 2048
    float* acts= eas + 2048;         // 1027
    float* wsum= acts + 1027;        // 16
    int* offs  = (int*)(wsum + 16);  // 65
    int* srcs  = offs + 65;          // 1024
    int* dsts  = srcs + NE;          // 1024
    int* sdst  = dsts + NE;          // 1024

    const int b   = blockIdx.x;
    const int tid = threadIdx.x;
    const int w   = tid >> 5;
    const int k   = tid & 31;

    // ---- cooperative loads ----
    for (int i = tid; i < 320;  i += T) W1s[i] = W1[i];
    for (int i = tid; i < 1024; i += T) W2s[i] = W2[i];
    for (int i = tid; i < 2336; i += T) Wls[i] = Wl[i];
    if (tid < 32) { b1s[tid] = b1[tid]; b2s[tid] = b2[tid];
                    bls[tid] = bl[tid]; Wvs[tid] = Wv[tid]; }
    for (int i = tid; i < 256;   i += T) xs[i]   = x[b * 256 + i];
    for (int i = tid; i < NROWS; i += T) acts[i] = action[b * NROWS + i];
    for (int i = tid; i < NE;    i += T) {
        srcs[i] = esrc[i]; dsts[i] = edst[i]; sdst[i] = g_sdst[i];
    }
    if (tid <= NN) offs[tid] = g_off[tid];
    for (int i = tid; i < NE; i += T) {
        int e = g_seidx[i];
        float2 v = ((const float2*)edge_attr)[b * NE + e];
        eas[2 * i] = v.x; eas[2 * i + 1] = v.y;
    }
    __syncthreads();

    // ---- p1[n,j] = x[n]@W1[0:4], p2[n,j] = x[n]@W1[4:8] ----
    for (int i = tid; i < NN * HID; i += T) {
        int n = i >> 5, j = i & 31;
        float x0 = xs[n*4+0], x1 = xs[n*4+1], x2 = xs[n*4+2], x3 = xs[n*4+3];
        p1s[i] = fmaf(x0, W1s[j],       fmaf(x1, W1s[32+j],
                 fmaf(x2, W1s[64+j],    x3 * W1s[96+j])));
        p2s[i] = fmaf(x0, W1s[128+j],   fmaf(x1, W1s[160+j],
                 fmaf(x2, W1s[192+j],   x3 * W1s[224+j])));
    }
    __syncthreads();

    // ---- H[n,j] = sum over edges of node n of relu(pre) (CSR gather, no atomics) ----
    {
        float w8 = W1s[256 + k], w9 = W1s[288 + k], b1k = b1s[k];
        #pragma unroll
        for (int nn = 0; nn < 4; nn++) {
            int n = w * 4 + nn;
            int beg = offs[n], end = offs[n + 1];
            float pbase = p1s[n * 32 + k] + b1k;
            float acc = 0.f;
            for (int i = beg; i < end; i++) {
                int d = sdst[i];
                float pre = fmaf(eas[2*i], w8,
                            fmaf(eas[2*i+1], w9, pbase + p2s[d * 32 + k]));
                acc += fmaxf(pre, 0.f);
            }
            Hs[n * 32 + k] = acc;
        }
    }
    __syncthreads();

    // ---- h[n] = [x[n], H[n]@W2 + deg*b2] ----
    for (int i = tid; i < 256; i += T) {        // copy x into h
        int n = i >> 2, c = i & 3;
        hsm[n * 36 + c] = xs[i];
    }
    {
        float w2c[32];
        #pragma unroll
        for (int j = 0; j < 32; j++) w2c[j] = W2s[j * 32 + k];
        float b2k = b2s[k];
        #pragma unroll
        for (int nn = 0; nn < 4; nn++) {
            int n = w * 4 + nn;
            float acc = (float)(offs[n + 1] - offs[n]) * b2k;
            #pragma unroll
            for (int j = 0; j < 32; j++)
                acc = fmaf(Hs[n * 32 + j], w2c[j], acc);
            hsm[n * 36 + 4 + k] = acc;
        }
    }
    __syncthreads();

    // ---- g1[n,k] = h[n]@Wl[0:36,k], g2[n,k] = h[n]@Wl[36:72,k] ----
    #pragma unroll
    for (int nn = 0; nn < 4; nn++) {
        int n = w * 4 + nn;
        float a1 = 0.f, a2 = 0.f;
        #pragma unroll
        for (int d = 0; d < 36; d++) {
            float hv = hsm[n * 36 + d];
            a1 = fmaf(hv, Wls[d * 32 + k], a1);
            a2 = fmaf(hv, Wls[(36 + d) * 32 + k], a2);
        }
        g1s[n * 32 + k] = a1;
        g2s[n * 32 + k] = a2;
    }
    __syncthreads();

    // ---- rows: v = relu(g1[s1]+g2[s2]+act*Wl72+bl) @ Wv, accumulated ----
    {
        float wl72 = Wls[72 * 32 + k], blk = bls[k], wvk = Wvs[k];
        float vacc = 0.f;
        for (int r = w; r < NROWS; r += 16) {
            int s1, s2;
            if (r < NE) { s1 = srcs[r]; s2 = dsts[r]; }
            else        { s1 = NN - NF + (r - NE); s2 = s1; }
            float a = acts[r];
            float pre = g1s[s1 * 32 + k] + g2s[s2 * 32 + k] + fmaf(a, wl72, blk);
            vacc = fmaf(fmaxf(pre, 0.f), wvk, vacc);
        }
        #pragma unroll
        for (int o = 16; o > 0; o >>= 1)
            vacc += __shfl_xor_sync(0xffffffffu, vacc, o);
        if (k == 0) wsum[w] = vacc;
    }
    __syncthreads();
    if (tid == 0) {
        float tot = 0.f;
        #pragma unroll
        for (int i = 0; i < 16; i++) tot += wsum[i];
        out[b] = tot + (float)NROWS * bv[0];
    }
}

// ---------------------------------------------------------------------------
extern "C" void kernel_launch(void* const* d_in, const int* in_sizes, int n_in,
                              void* d_out, int out_size) {
    const float* x         = (const float*)d_in[0];
    // d_in[1] = edge_index: redundant (per-graph list + b*64 offsets), unused
    const float* edge_attr = (const float*)d_in[2];
    const float* action    = (const float*)d_in[3];
    const int*   esrc      = (const int*)d_in[4];
    const int*   edst      = (const int*)d_in[5];
    const float* W1        = (const float*)d_in[6];
    const float* b1        = (const float*)d_in[7];
    const float* W2        = (const float*)d_in[8];
    const float* b2        = (const float*)d_in[9];
    const float* Wl        = (const float*)d_in[10];
    const float* bl        = (const float*)d_in[11];
    const float* Wv        = (const float*)d_in[12];
    const float* bv        = (const float*)d_in[13];
    float* out = (float*)d_out;

    cudaFuncSetAttribute(critic_kernel,
                         cudaFuncAttributeMaxDynamicSharedMemorySize,
                         SMEM_BYTES);

    build_csr<<<1, NE>>>(esrc, edst);
    critic_kernel<<<out_size, T, SMEM_BYTES>>>(
        x, edge_attr, action, esrc, edst,
        W1, b1, W2, b2, Wl, bl, Wv, bv, out);
}

// round 2
// speedup vs baseline: 1.3307x; 1.3307x over previous
#include <cuda_runtime.h>

#define NN    64          // nodes per graph
#define HID   32
#define NE    1024        // edges per graph
#define NF    3
#define NROWS (NE + NF)   // 1027
#define T     512         // threads per block

// CSR scratch (edge list is identical for every graph)
__device__ int g_off[NN + 1];
__device__ int g_sdst[NE];
__device__ int g_seidx[NE];

// ---------------------------------------------------------------------------
// Kernel 0: deterministic stable counting-sort of the 1024-edge list by src.
// Counting via integer atomics (order independent); ranks via a single-warp
// match_any scan over 32 chunks (deterministic, ~32 iterations).
// ---------------------------------------------------------------------------
__global__ void build_csr(const int* __restrict__ esrc,
                          const int* __restrict__ edst) {
    __shared__ int cnt[NN];
    __shared__ int offs[NN + 1];
    __shared__ int cnt2[NN];
    int t = threadIdx.x;            // blockDim = 1024
    if (t < NN) { cnt[t] = 0; cnt2[t] = 0; }
    __syncthreads();
    atomicAdd(&cnt[esrc[t]], 1);
    __syncthreads();
    if (t == 0) {
        int acc = 0;
        for (int n = 0; n < NN; n++) { offs[n] = acc; acc += cnt[n]; }
        offs[NN] = acc;
    }
    __syncthreads();
    if (t < 32) {
        for (int c = 0; c < NE / 32; c++) {
            int e = c * 32 + t;
            int s = esrc[e];
            unsigned m = __match_any_sync(0xffffffffu, s);
            int within = __popc(m & ((1u << t) - 1u));
            int base = cnt2[s];
            __syncwarp();
            int pos = offs[s] + base + within;
            g_sdst[pos]  = edst[e];
            g_seidx[pos] = e;
            if (within == 0) cnt2[s] = base + __popc(m);
            __syncwarp();
        }
    }
    if (t <= NN) g_off[t] = offs[t];
}

// ---------------------------------------------------------------------------
// Kernel 1: one block per graph. Entire graph state lives in shared memory.
// ---------------------------------------------------------------------------
// float words:
//  W1s 320 | b1s 32 | W2s 1024 | b2s 32 | Wls 2336 | bls 32 | Wvs 32 | xs 256
//  p1s 2048 | p2s 2048 | Hs 2048 | hsm 2304 | g1s 2048 | g2s 2048
//  ecomb 4096 (float4 x 1024) | acts 1028 | wsum 16
// int words: offs 68 (padded) | spack 1028
#define SMEM_WORDS (320+32+1024+32+2336+32+32+256 \
                    +2048+2048+2048+2304+2048+2048 \
                    +4096+1028+16 + 68+1028)
#define SMEM_BYTES (SMEM_WORDS * 4)

__global__ __launch_bounds__(T, 2) void critic_kernel(
    const float* __restrict__ x,         // [B*64, 4]
    const float* __restrict__ edge_attr, // [B*1024, 2]
    const float* __restrict__ action,    // [B, 1027]
    const int*   __restrict__ esrc,      // [1024]
    const int*   __restrict__ edst,      // [1024]
    const float* __restrict__ W1,        // [10,32]
    const float* __restrict__ b1,        // [32]
    const float* __restrict__ W2,        // [32,32]
    const float* __restrict__ b2,        // [32]
    const float* __restrict__ Wl,        // [73,32]
    const float* __restrict__ bl,        // [32]
    const float* __restrict__ Wv,        // [32]
    const float* __restrict__ bv,        // [1]
    float* __restrict__ out)             // [B]
{
    extern __shared__ float sm[];
    float* W1s = sm;                   // 320
    float* b1s = W1s + 320;            // 32
    float* W2s = b1s + 32;             // 1024
    float* b2s = W2s + 1024;           // 32
    float* Wls = b2s + 32;             // 2336
    float* bls = Wls + 2336;           // 32
    float* Wvs = bls + 32;             // 32
    float* xs  = Wvs + 32;             // 256   (off 4064 -> %4==0)
    float* p1s = xs  + 256;            // 2048
    float* p2s = p1s + 2048;           // 2048
    float* Hs  = p2s + 2048;           // 2048  (%4==0)
    float* hsm = Hs  + 2048;           // 2304  (%4==0, 64 x 36)
    float* g1s = hsm + 2304;           // 2048
    float* g2s = g1s + 2048;           // 2048
    float* ecf = g2s + 2048;           // 4096  (%4==0, float4[1024])
    float* acts= ecf + 4096;           // 1028  (%4==0)
    float* wsum= acts + 1028;          // 16
    int* offs  = (int*)(wsum + 16);    // 68 (padded)
    int* spack = offs + 68;            // 1028 (%4==0)
    float4* ecomb = (float4*)ecf;

    const int b   = blockIdx.x;
    const int tid = threadIdx.x;
    const int w   = tid >> 5;
    const int k   = tid & 31;

    // ---- cooperative loads ----
    for (int i = tid; i < 320;  i += T) W1s[i] = W1[i];
    for (int i = tid; i < 1024; i += T) W2s[i] = W2[i];
    for (int i = tid; i < 2336; i += T) Wls[i] = Wl[i];
    if (tid < 32) { b1s[tid] = b1[tid]; b2s[tid] = b2[tid];
                    bls[tid] = bl[tid]; Wvs[tid] = Wv[tid]; }
    for (int i = tid; i < 256;   i += T) xs[i]   = x[b * 256 + i];
    for (int i = tid; i < NROWS; i += T) acts[i] = action[b * NROWS + i];
    for (int i = tid; i < NE; i += T) {
        // row-loop endpoint pack (original edge order)
        spack[i] = esrc[i] | (edst[i] << 8);
        // edge-loop combined record (CSR order)
        int e = g_seidx[i];
        float2 v = ((const float2*)edge_attr)[b * NE + e];
        ecomb[i] = make_float4(v.x, v.y, __int_as_float(g_sdst[i]), 0.f);
    }
    if (tid < NF) {
        int n = NN - NF + tid;
        spack[NE + tid] = n | (n << 8);
    }
    if (tid == 0) { spack[NROWS] = 0; acts[NROWS] = 0.f; }
    if (tid <= NN) offs[tid] = g_off[tid];
    __syncthreads();

    // ---- p1[n,j] = x[n]@W1[0:4] + b1 (b1 folded), p2[n,j] = x[n]@W1[4:8] ----
    for (int i = tid; i < NN * HID; i += T) {
        int n = i >> 5, j = i & 31;
        float4 xv = *(const float4*)(xs + n * 4);
        p1s[i] = fmaf(xv.x, W1s[j],     fmaf(xv.y, W1s[32+j],
                 fmaf(xv.z, W1s[64+j],  fmaf(xv.w, W1s[96+j], b1s[j]))));
        p2s[i] = fmaf(xv.x, W1s[128+j], fmaf(xv.y, W1s[160+j],
                 fmaf(xv.z, W1s[192+j], xv.w * W1s[224+j])));
    }
    __syncthreads();

    // ---- H[n,k] = sum_{edges of n} relu(p1[n]+p2[dst]+ea@W1[8:10]) ----
    {
        float w8 = W1s[256 + k], w9 = W1s[288 + k];
        #pragma unroll
        for (int nn = 0; nn < 4; nn++) {
            int n = w * 4 + nn;
            int beg = offs[n], end = offs[n + 1];
            float pbase = p1s[n * 32 + k];
            float acc = 0.f;
            #pragma unroll 2
            for (int i = beg; i < end; i++) {
                float4 ec = ecomb[i];                 // 1 LDS.128 broadcast
                int d = __float_as_int(ec.z);
                float pre = fmaf(ec.x, w8,
                            fmaf(ec.y, w9, pbase + p2s[d * 32 + k]));
                acc += fmaxf(pre, 0.f);
            }
            Hs[n * 32 + k] = acc;
        }
    }
    __syncthreads();

    // ---- h[n] = [x[n], H[n]@W2 + deg*b2] ----
    for (int i = tid; i < 256; i += T) {        // copy x into h
        int n = i >> 2, c = i & 3;
        hsm[n * 36 + c] = xs[i];
    }
    {
        float w2c[32];
        #pragma unroll
        for (int j = 0; j < 32; j++) w2c[j] = W2s[j * 32 + k];
        float b2k = b2s[k];
        #pragma unroll
        for (int nn = 0; nn < 4; nn++) {
            int n = w * 4 + nn;
            float acc = (float)(offs[n + 1] - offs[n]) * b2k;
            const float4* hp = (const float4*)(Hs + n * 32);
            #pragma unroll
            for (int q = 0; q < 8; q++) {
                float4 hv = hp[q];                    // LDS.128 broadcast
                acc = fmaf(hv.x, w2c[4*q+0], acc);
                acc = fmaf(hv.y, w2c[4*q+1], acc);
                acc = fmaf(hv.z, w2c[4*q+2], acc);
                acc = fmaf(hv.w, w2c[4*q+3], acc);
            }
            hsm[n * 36 + 4 + k] = acc;
        }
    }
    __syncthreads();

    // ---- g1[n,k] = h[n]@Wl[0:36,k] + bl (folded), g2[n,k] = h[n]@Wl[36:72,k] ----
    #pragma unroll 1
    for (int half = 0; half < 2; half++) {
        float wreg[36];
        const float* wbase = Wls + (half ? 36 * 32 : 0);
        #pragma unroll
        for (int d = 0; d < 36; d++) wreg[d] = wbase[d * 32 + k];
        float* gout = half ? g2s : g1s;
        float init = half ? 0.f : bls[k];
        #pragma unroll
        for (int nn = 0; nn < 4; nn++) {
            int n = w * 4 + nn;
            float acc = init;
            const float4* hp = (const float4*)(hsm + n * 36);
            #pragma unroll
            for (int q = 0; q < 9; q++) {
                float4 hv = hp[q];                    // LDS.128 broadcast
                acc = fmaf(hv.x, wreg[4*q+0], acc);
                acc = fmaf(hv.y, wreg[4*q+1], acc);
                acc = fmaf(hv.z, wreg[4*q+2], acc);
                acc = fmaf(hv.w, wreg[4*q+3], acc);
            }
            gout[n * 32 + k] = acc;
        }
    }
    __syncthreads();

    // ---- rows: v = relu(g1[s1]+g2[s2]+act*Wl[72]) @ Wv, accumulated ----
    {
        float wl72 = Wls[72 * 32 + k], wvk = Wvs[k];
        float vacc = 0.f;
        for (int base = w * 4; base < NROWS; base += 64) {
            float4 av = *(const float4*)(acts + base);
            int4  sp = *(const int4*)(spack + base);
            {
                int s1 = sp.x & 0xff, s2 = sp.x >> 8;
                float pre = g1s[s1*32+k] + g2s[s2*32+k] + av.x * wl72;
                vacc = fmaf(fmaxf(pre, 0.f), wvk, vacc);
            }
            if (base + 1 < NROWS) {
                int s1 = sp.y & 0xff, s2 = sp.y >> 8;
                float pre = g1s[s1*32+k] + g2s[s2*32+k] + av.y * wl72;
                vacc = fmaf(fmaxf(pre, 0.f), wvk, vacc);
            }
            if (base + 2 < NROWS) {
                int s1 = sp.z & 0xff, s2 = sp.z >> 8;
                float pre = g1s[s1*32+k] + g2s[s2*32+k] + av.z * wl72;
                vacc = fmaf(fmaxf(pre, 0.f), wvk, vacc);
            }
            if (base + 3 < NROWS) {
                int s1 = sp.w & 0xff, s2 = sp.w >> 8;
                float pre = g1s[s1*32+k] + g2s[s2*32+k] + av.w * wl72;
                vacc = fmaf(fmaxf(pre, 0.f), wvk, vacc);
            }
        }
        #pragma unroll
        for (int o = 16; o > 0; o >>= 1)
            vacc += __shfl_xor_sync(0xffffffffu, vacc, o);
        if (k == 0) wsum[w] = vacc;
    }
    __syncthreads();
    if (tid == 0) {
        float tot = 0.f;
        #pragma unroll
        for (int i = 0; i < 16; i++) tot += wsum[i];
        out[b] = tot + (float)NROWS * bv[0];
    }
}

// ---------------------------------------------------------------------------
extern "C" void kernel_launch(void* const* d_in, const int* in_sizes, int n_in,
                              void* d_out, int out_size) {
    const float* x         = (const float*)d_in[0];
    // d_in[1] = edge_index: redundant (per-graph list + b*64 offsets), unused
    const float* edge_attr = (const float*)d_in[2];
    const float* action    = (const float*)d_in[3];
    const int*   esrc      = (const int*)d_in[4];
    const int*   edst      = (const int*)d_in[5];
    const float* W1        = (const float*)d_in[6];
    const float* b1        = (const float*)d_in[7];
    const float* W2        = (const float*)d_in[8];
    const float* b2        = (const float*)d_in[9];
    const float* Wl        = (const float*)d_in[10];
    const float* bl        = (const float*)d_in[11];
    const float* Wv        = (const float*)d_in[12];
    const float* bv        = (const float*)d_in[13];
    float* out = (float*)d_out;

    cudaFuncSetAttribute(critic_kernel,
                         cudaFuncAttributeMaxDynamicSharedMemorySize,
                         SMEM_BYTES);

    build_csr<<<1, NE>>>(esrc, edst);
    critic_kernel<<<out_size, T, SMEM_BYTES>>>(
        x, edge_attr, action, esrc, edst,
        W1, b1, W2, b2, Wl, bl, Wv, bv, out);
}

// round 3
// speedup vs baseline: 1.4633x; 1.0997x over previous
#include <cuda_runtime.h>

#define NN    64          // nodes per graph
#define HID   32
#define NE    1024        // edges per graph
#define NF    3
#define NROWS (NE + NF)   // 1027
#define T     512

// batch-invariant scratch (edge list & weights identical for every graph)
__device__ int   g_off[NN + 1];
__device__ int   g_sdst[NE];
__device__ int   g_seidx[NE];
__device__ float g_M1[HID * HID];   // W2 @ Wl[4:36]
__device__ float g_M2[HID * HID];   // W2 @ Wl[40:72]
__device__ float g_c1[HID];         // b2 @ Wl[4:36]
__device__ float g_c2[HID];         // b2 @ Wl[40:72]

// ---------------------------------------------------------------------------
// Kernel 0: CSR build (deterministic stable counting sort) + weight folding.
// ---------------------------------------------------------------------------
__global__ void setup_kernel(const int* __restrict__ esrc,
                             const int* __restrict__ edst,
                             const float* __restrict__ W2,
                             const float* __restrict__ Wl,
                             const float* __restrict__ b2) {
    __shared__ int cnt[NN];
    __shared__ int offs[NN + 1];
    __shared__ int cnt2[NN];
    int t = threadIdx.x;            // blockDim = 1024
    if (t < NN) { cnt[t] = 0; cnt2[t] = 0; }
    __syncthreads();
    atomicAdd(&cnt[esrc[t]], 1);
    __syncthreads();
    if (t == 0) {
        int acc = 0;
        for (int n = 0; n < NN; n++) { offs[n] = acc; acc += cnt[n]; }
        offs[NN] = acc;
    }
    __syncthreads();
    if (t < 32) {
        for (int c = 0; c < NE / 32; c++) {
            int e = c * 32 + t;
            int s = esrc[e];
            unsigned m = __match_any_sync(0xffffffffu, s);
            int within = __popc(m & ((1u << t) - 1u));
            int base = cnt2[s];
            __syncwarp();
            int pos = offs[s] + base + within;
            g_sdst[pos]  = edst[e];
            g_seidx[pos] = e;
            if (within == 0) cnt2[s] = base + __popc(m);
            __syncwarp();
        }
    }
    if (t <= NN) g_off[t] = offs[t];

    // fold W2 through Wl: M1[t,k] = sum_j W2[t,j] * Wl[4+j,k]  (and 40+j)
    int tt = t >> 5, k = t & 31;
    float a1 = 0.f, a2 = 0.f;
    for (int j = 0; j < 32; j++) {
        float w2 = W2[tt * 32 + j];
        a1 = fmaf(w2, Wl[(4  + j) * 32 + k], a1);
        a2 = fmaf(w2, Wl[(40 + j) * 32 + k], a2);
    }
    g_M1[t] = a1;
    g_M2[t] = a2;
    if (t < 32) {
        float c1 = 0.f, c2 = 0.f;
        for (int j = 0; j < 32; j++) {
            c1 = fmaf(b2[j], Wl[(4  + j) * 32 + t], c1);
            c2 = fmaf(b2[j], Wl[(40 + j) * 32 + t], c2);
        }
        g_c1[t] = c1;
        g_c2[t] = c2;
    }
}

// ---------------------------------------------------------------------------
// Kernel 1: one block per graph. 68.4 KB smem -> 3 blocks/SM.
// ---------------------------------------------------------------------------
// float layout:
//  0     W1s   320
//  320   b1s   32
//  352   Xl1   128   (Wl rows 0..3)
//  480   Xl2   128   (Wl rows 36..39)
//  608   wl72s 32    (Wl row 72)
//  640   bls   32
//  672   Wvs   32
//  704   c1s   32
//  736   c2s   32
//  768   xs    256
//  1024  M1s   1024
//  2048  M2s   1024
//  3072  p1s   2048
//  5120  p2s   2048
//  7168  Hs    2048
//  9216  g1s   2048
//  11264 g2s   2048
//  13312 ecomb 4096  (float4[1024]: ea0, ea1, dst_bits, act)
//  17408 facta 4
//  17412 wsum  16
//  17428 offs  68 (int)
#define SMEM_WORDS 17496
#define SMEM_BYTES (SMEM_WORDS * 4)

__global__ __launch_bounds__(T, 3) void critic_kernel(
    const float* __restrict__ x,         // [B*64, 4]
    const float* __restrict__ edge_attr, // [B*1024, 2]
    const float* __restrict__ action,    // [B, 1027]
    const float* __restrict__ W1,        // [10,32]
    const float* __restrict__ b1,        // [32]
    const float* __restrict__ Wl,        // [73,32]
    const float* __restrict__ bl,        // [32]
    const float* __restrict__ Wv,        // [32]
    const float* __restrict__ bv,        // [1]
    float* __restrict__ out)             // [B]
{
    extern __shared__ float sm[];
    float* W1s   = sm;
    float* b1s   = sm + 320;
    float* Xl1   = sm + 352;
    float* Xl2   = sm + 480;
    float* wl72s = sm + 608;
    float* bls   = sm + 640;
    float* Wvs   = sm + 672;
    float* c1s   = sm + 704;
    float* c2s   = sm + 736;
    float* xs    = sm + 768;
    float* M1s   = sm + 1024;
    float* M2s   = sm + 2048;
    float* p1s   = sm + 3072;
    float* p2s   = sm + 5120;
    float* Hs    = sm + 7168;
    float* g1s   = sm + 9216;
    float* g2s   = sm + 11264;
    float* ecf   = sm + 13312;
    float* facta = sm + 17408;
    float* wsum  = sm + 17412;
    int*   offs  = (int*)(sm + 17428);
    float4* ecomb = (float4*)ecf;

    const int b   = blockIdx.x;
    const int tid = threadIdx.x;
    const int w   = tid >> 5;
    const int k   = tid & 31;

    // ---- cooperative loads ----
    for (int i = tid; i < 320; i += T) W1s[i] = W1[i];
    if (tid < 128) { Xl1[tid] = Wl[tid]; Xl2[tid] = Wl[36 * 32 + tid]; }
    if (tid < 32) {
        b1s[tid]   = b1[tid];
        wl72s[tid] = Wl[72 * 32 + tid];
        bls[tid]   = bl[tid];
        Wvs[tid]   = Wv[tid];
        c1s[tid]   = g_c1[tid];
        c2s[tid]   = g_c2[tid];
    }
    for (int i = tid; i < 1024; i += T) { M1s[i] = g_M1[i]; M2s[i] = g_M2[i]; }
    for (int i = tid; i < 256; i += T) xs[i] = x[b * 256 + i];
    for (int i = tid; i < NE; i += T) {
        int e = g_seidx[i];
        float2 v = ((const float2*)edge_attr)[b * NE + e];
        float  a = action[b * NROWS + e];
        ecomb[i] = make_float4(v.x, v.y, __int_as_float(g_sdst[i]), a);
    }
    if (tid < NF) facta[tid] = action[b * NROWS + NE + tid];
    if (tid <= NN) offs[tid] = g_off[tid];
    __syncthreads();

    // ---- per-node precomputes: p1,p2 (EdgeConv layer1), g init (x part) ----
    for (int i = tid; i < NN * HID; i += T) {
        int n = i >> 5, j = i & 31;
        float4 xv = *(const float4*)(xs + n * 4);
        p1s[i] = fmaf(xv.x, W1s[j],       fmaf(xv.y, W1s[32 + j],
                 fmaf(xv.z, W1s[64 + j],  fmaf(xv.w, W1s[96 + j], b1s[j]))));
        p2s[i] = fmaf(xv.x, W1s[128 + j], fmaf(xv.y, W1s[160 + j],
                 fmaf(xv.z, W1s[192 + j], xv.w * W1s[224 + j])));
        g1s[i] = fmaf(xv.x, Xl1[j],       fmaf(xv.y, Xl1[32 + j],
                 fmaf(xv.z, Xl1[64 + j],  fmaf(xv.w, Xl1[96 + j], bls[j]))));
        g2s[i] = fmaf(xv.x, Xl2[j],       fmaf(xv.y, Xl2[32 + j],
                 fmaf(xv.z, Xl2[64 + j],  xv.w * Xl2[96 + j])));
    }
    __syncthreads();

    // ---- H[n,k] = sum_{edges of n} relu(p1[n]+p2[dst]+ea@W1[8:10]) ----
    {
        float w8 = W1s[256 + k], w9 = W1s[288 + k];
        #pragma unroll
        for (int nn = 0; nn < 4; nn++) {
            int n = w * 4 + nn;
            int beg = offs[n], end = offs[n + 1];
            float pbase = p1s[n * 32 + k];
            float acc = 0.f;
            #pragma unroll 2
            for (int i = beg; i < end; i++) {
                float4 ec = ecomb[i];                 // LDS.128 broadcast
                int d = __float_as_int(ec.z);
                float pre = fmaf(ec.x, w8,
                            fmaf(ec.y, w9, pbase + p2s[d * 32 + k]));
                acc += fmaxf(pre, 0.f);
            }
            Hs[n * 32 + k] = acc;
        }
    }
    __syncthreads();

    // ---- g{1,2}[n,k] += H[n]@M{1,2} + deg*c{1,2}; warps 0-7: g1, 8-15: g2 ----
    {
        int half = w >> 3, wl = w & 7;
        const float* Ms  = half ? M2s : M1s;
        float*       gsd = half ? g2s : g1s;
        float ck = half ? c2s[k] : c1s[k];
        float Mreg[32];
        #pragma unroll
        for (int j = 0; j < 32; j++) Mreg[j] = Ms[j * 32 + k];
        #pragma unroll
        for (int nn = 0; nn < 8; nn++) {
            int n = wl * 8 + nn;
            float acc = fmaf((float)(offs[n + 1] - offs[n]), ck, gsd[n * 32 + k]);
            const float4* hp = (const float4*)(Hs + n * 32);
            #pragma unroll
            for (int q = 0; q < 8; q++) {
                float4 hv = hp[q];                    // LDS.128 broadcast
                acc = fmaf(hv.x, Mreg[4 * q + 0], acc);
                acc = fmaf(hv.y, Mreg[4 * q + 1], acc);
                acc = fmaf(hv.z, Mreg[4 * q + 2], acc);
                acc = fmaf(hv.w, Mreg[4 * q + 3], acc);
            }
            gsd[n * 32 + k] = acc;
        }
    }
    __syncthreads();

    // ---- rows (CSR order): v = relu(g1[src]+g2[dst]+act*wl72) @ Wv ----
    {
        float wl72k = wl72s[k], wvk = Wvs[k];
        float vacc = 0.f;
        #pragma unroll
        for (int nn = 0; nn < 4; nn++) {
            int n = w * 4 + nn;
            int beg = offs[n], end = offs[n + 1];
            float g1k = g1s[n * 32 + k];              // src fixed per node
            #pragma unroll 2
            for (int i = beg; i < end; i++) {
                float4 ec = ecomb[i];                 // .z=dst, .w=act
                int d = __float_as_int(ec.z);
                float pre = fmaf(ec.w, wl72k, g1k) + g2s[d * 32 + k];
                vacc = fmaf(fmaxf(pre, 0.f), wvk, vacc);
            }
        }
        if (w < NF) {                                 // factory rows
            int n = NN - NF + w;
            float pre = g1s[n * 32 + k] + g2s[n * 32 + k] + facta[w] * wl72k;
            vacc = fmaf(fmaxf(pre, 0.f), wvk, vacc);
        }
        #pragma unroll
        for (int o = 16; o > 0; o >>= 1)
            vacc += __shfl_xor_sync(0xffffffffu, vacc, o);
        if (k == 0) wsum[w] = vacc;
    }
    __syncthreads();
    if (tid == 0) {
        float tot = 0.f;
        #pragma unroll
        for (int i = 0; i < 16; i++) tot += wsum[i];
        out[b] = tot + (float)NROWS * bv[0];
    }
}

// ---------------------------------------------------------------------------
extern "C" void kernel_launch(void* const* d_in, const int* in_sizes, int n_in,
                              void* d_out, int out_size) {
    const float* x         = (const float*)d_in[0];
    // d_in[1] = edge_index: redundant, unused
    const float* edge_attr = (const float*)d_in[2];
    const float* action    = (const float*)d_in[3];
    const int*   esrc      = (const int*)d_in[4];
    const int*   edst      = (const int*)d_in[5];
    const float* W1        = (const float*)d_in[6];
    const float* b1        = (const float*)d_in[7];
    const float* W2        = (const float*)d_in[8];
    const float* b2        = (const float*)d_in[9];
    const float* Wl        = (const float*)d_in[10];
    const float* bl        = (const float*)d_in[11];
    const float* Wv        = (const float*)d_in[12];
    const float* bv        = (const float*)d_in[13];
    float* out = (float*)d_out;

    cudaFuncSetAttribute(critic_kernel,
                         cudaFuncAttributeMaxDynamicSharedMemorySize,
                         SMEM_BYTES);

    setup_kernel<<<1, 1024>>>(esrc, edst, W2, Wl, b2);
    critic_kernel<<<out_size, T, SMEM_BYTES>>>(
        x, edge_attr, action, W1, b1, Wl, bl, Wv, bv, out);
}

// round 4
// speedup vs baseline: 1.6306x; 1.1143x over previous
#include <cuda_runtime.h>

#define NN    64          // nodes per graph
#define HID   32
#define NE    1024        // edges per graph
#define NF    3
#define NROWS (NE + NF)   // 1027
#define T     512

// batch-invariant scratch (edge list & weights identical for every graph)
__device__ int   g_off[NN + 1];
__device__ int   g_rank[NE];        // CSR slot of original edge e
__device__ float g_M1[HID * HID];   // W2 @ Wl[4:36]
__device__ float g_M2[HID * HID];   // W2 @ Wl[40:72]
__device__ float g_c1[HID];         // b2 @ Wl[4:36]
__device__ float g_c2[HID];         // b2 @ Wl[40:72]

// ---------------------------------------------------------------------------
// Kernel 0: CSR rank build (deterministic stable counting sort) + weight fold.
// ---------------------------------------------------------------------------
__global__ void setup_kernel(const int* __restrict__ esrc,
                             const int* __restrict__ edst,
                             const float* __restrict__ W2,
                             const float* __restrict__ Wl,
                             const float* __restrict__ b2) {
    __shared__ int cnt[NN];
    __shared__ int offs[NN + 1];
    __shared__ int cnt2[NN];
    int t = threadIdx.x;            // blockDim = 1024
    if (t < NN) { cnt[t] = 0; cnt2[t] = 0; }
    __syncthreads();
    atomicAdd(&cnt[esrc[t]], 1);
    __syncthreads();
    if (t == 0) {
        int acc = 0;
        for (int n = 0; n < NN; n++) { offs[n] = acc; acc += cnt[n]; }
        offs[NN] = acc;
    }
    __syncthreads();
    if (t < 32) {
        for (int c = 0; c < NE / 32; c++) {
            int e = c * 32 + t;
            int s = esrc[e];
            unsigned m = __match_any_sync(0xffffffffu, s);
            int within = __popc(m & ((1u << t) - 1u));
            int base = cnt2[s];
            __syncwarp();
            g_rank[e] = offs[s] + base + within;
            if (within == 0) cnt2[s] = base + __popc(m);
            __syncwarp();
        }
    }
    if (t <= NN) g_off[t] = offs[t];

    // fold W2 through Wl: M1[t,k] = sum_j W2[t,j] * Wl[4+j,k]  (and 40+j)
    int tt = t >> 5, k = t & 31;
    float a1 = 0.f, a2 = 0.f;
    for (int j = 0; j < 32; j++) {
        float w2 = W2[tt * 32 + j];
        a1 = fmaf(w2, Wl[(4  + j) * 32 + k], a1);
        a2 = fmaf(w2, Wl[(40 + j) * 32 + k], a2);
    }
    g_M1[t] = a1;
    g_M2[t] = a2;
    if (t < 32) {
        float c1 = 0.f, c2 = 0.f;
        for (int j = 0; j < 32; j++) {
            c1 = fmaf(b2[j], Wl[(4  + j) * 32 + t], c1);
            c2 = fmaf(b2[j], Wl[(40 + j) * 32 + t], c2);
        }
        g_c1[t] = c1;
        g_c2[t] = c2;
    }
}

// ---------------------------------------------------------------------------
// Kernel 1: one block per graph. ~68.4 KB smem -> 3 blocks/SM.
// ---------------------------------------------------------------------------
#define SMEM_WORDS 17496
#define SMEM_BYTES (SMEM_WORDS * 4)

__global__ __launch_bounds__(T, 3) void critic_kernel(
    const float* __restrict__ x,         // [B*64, 4]
    const float* __restrict__ edge_attr, // [B*1024, 2]
    const float* __restrict__ action,    // [B, 1027]
    const int*   __restrict__ edst,      // [1024]
    const float* __restrict__ W1,        // [10,32]
    const float* __restrict__ b1,        // [32]
    const float* __restrict__ Wl,        // [73,32]
    const float* __restrict__ bl,        // [32]
    const float* __restrict__ Wv,        // [32]
    const float* __restrict__ bv,        // [1]
    float* __restrict__ out)             // [B]
{
    extern __shared__ float sm[];
    float* W1s   = sm;          // 320
    float* b1s   = sm + 320;    // 32
    float* Xl1   = sm + 352;    // 128 (Wl rows 0..3)
    float* Xl2   = sm + 480;    // 128 (Wl rows 36..39)
    float* wl72s = sm + 608;    // 32
    float* bls   = sm + 640;    // 32
    float* Wvs   = sm + 672;    // 32
    float* c1s   = sm + 704;    // 32
    float* c2s   = sm + 736;    // 32
    float* xs    = sm + 768;    // 256
    float* M1s   = sm + 1024;   // 1024
    float* M2s   = sm + 2048;   // 1024
    float* p1s   = sm + 3072;   // 2048
    float* p2s   = sm + 5120;   // 2048
    float* Hs    = sm + 7168;   // 2048
    float* g1s   = sm + 9216;   // 2048
    float* g2s   = sm + 11264;  // 2048
    float* ecf   = sm + 13312;  // 4096 (float4[1024]: ea0, ea1, dst, act)
    float* facta = sm + 17408;  // 4
    float* wsum  = sm + 17412;  // 16
    int*   offs  = (int*)(sm + 17428); // 68
    float4* ecomb = (float4*)ecf;

    const int b    = blockIdx.x;
    const int tid  = threadIdx.x;
    const int w    = tid >> 5;
    const int k    = tid & 31;
    const int half = k >> 4;         // edge-pair half
    const int m    = k & 15;         // k-pair index (covers k = 2m, 2m+1)

    // ---- cooperative loads (all coalesced) ----
    for (int i = tid; i < 320; i += T) W1s[i] = W1[i];
    if (tid < 128) { Xl1[tid] = Wl[tid]; Xl2[tid] = Wl[36 * 32 + tid]; }
    if (tid < 32) {
        b1s[tid]   = b1[tid];
        wl72s[tid] = Wl[72 * 32 + tid];
        bls[tid]   = bl[tid];
        Wvs[tid]   = Wv[tid];
        c1s[tid]   = g_c1[tid];
        c2s[tid]   = g_c2[tid];
    }
    for (int i = tid; i < 1024; i += T) { M1s[i] = g_M1[i]; M2s[i] = g_M2[i]; }
    for (int i = tid; i < 256; i += T) xs[i] = x[b * 256 + i];
    for (int i = tid; i < NE; i += T) {
        int   rk = g_rank[i];                               // coalesced
        float2 v = ((const float2*)edge_attr)[b * NE + i];  // coalesced
        float  a = action[b * NROWS + i];                   // coalesced
        int    d = edst[i];                                 // coalesced
        ecomb[rk] = make_float4(v.x, v.y, __int_as_float(d), a); // scattered STS
    }
    if (tid < NF) facta[tid] = action[b * NROWS + NE + tid];
    if (tid <= NN) offs[tid] = g_off[tid];
    __syncthreads();

    // ---- per-node precomputes: p1,p2 (EdgeConv layer1), g init (x part) ----
    for (int i = tid; i < NN * HID; i += T) {
        int n = i >> 5, j = i & 31;
        float4 xv = *(const float4*)(xs + n * 4);
        p1s[i] = fmaf(xv.x, W1s[j],       fmaf(xv.y, W1s[32 + j],
                 fmaf(xv.z, W1s[64 + j],  fmaf(xv.w, W1s[96 + j], b1s[j]))));
        p2s[i] = fmaf(xv.x, W1s[128 + j], fmaf(xv.y, W1s[160 + j],
                 fmaf(xv.z, W1s[192 + j], xv.w * W1s[224 + j])));
        g1s[i] = fmaf(xv.x, Xl1[j],       fmaf(xv.y, Xl1[32 + j],
                 fmaf(xv.z, Xl1[64 + j],  fmaf(xv.w, Xl1[96 + j], bls[j]))));
        g2s[i] = fmaf(xv.x, Xl2[j],       fmaf(xv.y, Xl2[32 + j],
                 fmaf(xv.z, Xl2[64 + j],  xv.w * Xl2[96 + j])));
    }
    __syncthreads();

    // ---- H[n,k] = sum_{edges of n} relu(p1[n]+p2[dst]+ea@W1[8:10]) ----
    // half-warp scheme: lanes 0-15 take even CSR slots, 16-31 odd; each lane
    // owns k-pair (2m, 2m+1).
    {
        float w8a = W1s[256 + 2 * m], w8b = W1s[256 + 2 * m + 1];
        float w9a = W1s[288 + 2 * m], w9b = W1s[288 + 2 * m + 1];
        #pragma unroll
        for (int nn = 0; nn < 4; nn++) {
            int n = w * 4 + nn;
            int beg = offs[n], end = offs[n + 1];
            float2 p1v = *(const float2*)(p1s + n * 32 + 2 * m);
            float aLo = 0.f, aHi = 0.f;
            for (int i = beg + half; i < end; i += 2) {
                float4 ec = ecomb[i];                          // 2x16B -> 1 wf
                int d = __float_as_int(ec.z);
                float2 p2v = *(const float2*)(p2s + d * 32 + 2 * m); // 2 wf
                float preA = fmaf(ec.x, w8a, fmaf(ec.y, w9a, p1v.x + p2v.x));
                float preB = fmaf(ec.x, w8b, fmaf(ec.y, w9b, p1v.y + p2v.y));
                aLo += fmaxf(preA, 0.f);
                aHi += fmaxf(preB, 0.f);
            }
            aLo += __shfl_xor_sync(0xffffffffu, aLo, 16);
            aHi += __shfl_xor_sync(0xffffffffu, aHi, 16);
            if (half == 0)
                *(float2*)(Hs + n * 32 + 2 * m) = make_float2(aLo, aHi);
        }
    }
    __syncthreads();

    // ---- g{1,2}[n,k] += H[n]@M{1,2} + deg*c{1,2}; warps 0-7: g1, 8-15: g2 ----
    {
        int hf = w >> 3, wl = w & 7;
        const float* Ms  = hf ? M2s : M1s;
        float*       gsd = hf ? g2s : g1s;
        float ck = hf ? c2s[k] : c1s[k];
        float Mreg[32];
        #pragma unroll
        for (int j = 0; j < 32; j++) Mreg[j] = Ms[j * 32 + k];
        #pragma unroll
        for (int nn = 0; nn < 8; nn++) {
            int n = wl * 8 + nn;
            float acc = fmaf((float)(offs[n + 1] - offs[n]), ck, gsd[n * 32 + k]);
            const float4* hp = (const float4*)(Hs + n * 32);
            #pragma unroll
            for (int q = 0; q < 8; q++) {
                float4 hv = hp[q];                    // LDS.128 broadcast
                acc = fmaf(hv.x, Mreg[4 * q + 0], acc);
                acc = fmaf(hv.y, Mreg[4 * q + 1], acc);
                acc = fmaf(hv.z, Mreg[4 * q + 2], acc);
                acc = fmaf(hv.w, Mreg[4 * q + 3], acc);
            }
            gsd[n * 32 + k] = acc;
        }
    }
    __syncthreads();

    // ---- rows (CSR order): v = relu(g1[src]+g2[dst]+act*wl72) @ Wv ----
    {
        float wlA = wl72s[2 * m], wlB = wl72s[2 * m + 1];
        float wvA = Wvs[2 * m],   wvB = Wvs[2 * m + 1];
        float vLo = 0.f, vHi = 0.f;
        #pragma unroll
        for (int nn = 0; nn < 4; nn++) {
            int n = w * 4 + nn;
            int beg = offs[n], end = offs[n + 1];
            float2 g1v = *(const float2*)(g1s + n * 32 + 2 * m);
            for (int i = beg + half; i < end; i += 2) {
                float4 ec = ecomb[i];
                int d = __float_as_int(ec.z);
                float2 g2v = *(const float2*)(g2s + d * 32 + 2 * m);
                float preA = fmaf(ec.w, wlA, g1v.x) + g2v.x;
                float preB = fmaf(ec.w, wlB, g1v.y) + g2v.y;
                vLo = fmaf(fmaxf(preA, 0.f), wvA, vLo);
                vHi = fmaf(fmaxf(preB, 0.f), wvB, vHi);
            }
        }
        if (w < NF && half == 0) {                    // factory rows (tiny)
            int n = NN - NF + w;
            float fa = facta[w];
            float2 g1v = *(const float2*)(g1s + n * 32 + 2 * m);
            float2 g2v = *(const float2*)(g2s + n * 32 + 2 * m);
            float preA = fmaf(fa, wlA, g1v.x) + g2v.x;
            float preB = fmaf(fa, wlB, g1v.y) + g2v.y;
            vLo = fmaf(fmaxf(preA, 0.f), wvA, vLo);
            vHi = fmaf(fmaxf(preB, 0.f), wvB, vHi);
        }
        float vacc = vLo + vHi;
        #pragma unroll
        for (int o = 16; o > 0; o >>= 1)
            vacc += __shfl_xor_sync(0xffffffffu, vacc, o);
        if (k == 0) wsum[w] = vacc;
    }
    __syncthreads();
    if (tid == 0) {
        float tot = 0.f;
        #pragma unroll
        for (int i = 0; i < 16; i++) tot += wsum[i];
        out[b] = tot + (float)NROWS * bv[0];
    }
}

// ---------------------------------------------------------------------------
extern "C" void kernel_launch(void* const* d_in, const int* in_sizes, int n_in,
                              void* d_out, int out_size) {
    const float* x         = (const float*)d_in[0];
    // d_in[1] = edge_index: redundant, unused
    const float* edge_attr = (const float*)d_in[2];
    const float* action    = (const float*)d_in[3];
    const int*   esrc      = (const int*)d_in[4];
    const int*   edst      = (const int*)d_in[5];
    const float* W1        = (const float*)d_in[6];
    const float* b1        = (const float*)d_in[7];
    const float* W2        = (const float*)d_in[8];
    const float* b2        = (const float*)d_in[9];
    const float* Wl        = (const float*)d_in[10];
    const float* bl        = (const float*)d_in[11];
    const float* Wv        = (const float*)d_in[12];
    const float* bv        = (const float*)d_in[13];
    float* out = (float*)d_out;

    cudaFuncSetAttribute(critic_kernel,
                         cudaFuncAttributeMaxDynamicSharedMemorySize,
                         SMEM_BYTES);

    setup_kernel<<<1, 1024>>>(esrc, edst, W2, Wl, b2);
    critic_kernel<<<out_size, T, SMEM_BYTES>>>(
        x, edge_attr, action, edst, W1, b1, Wl, bl, Wv, bv, out);
}